// round 1
// baseline (speedup 1.0000x reference)
#include <cuda_runtime.h>
#include <cuda_bf16.h>
#include <cstdint>

// Problem constants
#define TT 512
#define BB 64
#define II 1024
#define HH 1024
#define GM (TT*BB)     // 32768 rows of the input GEMM
#define GK II
#define GN HH

// Recurrent kernel config
#define NBLK 128       // persistent CTAs (<= 148 SMs, all resident)
#define JPB  8         // output columns per CTA (128*8 = 1024)
#define RTHREADS 256
#define CHUNK 256      // k-chunk of h staged in smem

// Scratch (static __device__ allocations only; no cudaMalloc allowed)
__device__ float g_gates[(size_t)3 * TT * BB * HH];  // xr/xz/xh pre-projections (402 MB)
__device__ float g_hT [(size_t)HH * BB];             // h transposed [j][b]
__device__ float g_hrT[(size_t)HH * BB];             // (h*reset) transposed [j][b]
__device__ unsigned g_bar_cnt;
__device__ unsigned g_bar_gen;

// ---------------------------------------------------------------------------
// Grid-wide barrier (all NBLK CTAs co-resident: grid <= SM count, 1 CTA/SM)
// ---------------------------------------------------------------------------
__device__ __forceinline__ void gridBarrier() {
    __syncthreads();
    if (threadIdx.x == 0) {
        __threadfence();                       // publish my writes
        volatile unsigned* vgen = &g_bar_gen;
        unsigned gen = *vgen;                  // read epoch BEFORE arriving
        if (atomicAdd(&g_bar_cnt, 1u) == NBLK - 1u) {
            g_bar_cnt = 0u;
            __threadfence();
            *vgen = gen + 1u;                  // release
        } else {
            while (*vgen == gen) { __nanosleep(32); }
        }
        __threadfence();                       // acquire others' writes
    }
    __syncthreads();
}

__device__ __forceinline__ float sigmoidf_(float x) {
    return 1.0f / (1.0f + __expf(-x));
}

// ---------------------------------------------------------------------------
// Input projection GEMM: C[m,n] = sum_k A[m,k] * W[n,k] + bias[n]
// A = x flattened [GM, GK], W = [GN, GK], C = g_gates + gate*GM*GN
// 128x128 tile, BK=16, 256 threads, 8x8 microtile.
// ---------------------------------------------------------------------------
__global__ __launch_bounds__(256) void sgemm_gate(
    const float* __restrict__ A,
    const float* __restrict__ W,
    const float* __restrict__ bias,
    int gate)
{
    __shared__ float As[16][128];
    __shared__ float Bs[16][128];

    float* C = g_gates + (size_t)gate * GM * GN;
    const int m0 = blockIdx.y * 128;
    const int n0 = blockIdx.x * 128;
    const int t  = threadIdx.x;
    const int rt = t >> 4;     // 0..15
    const int ct = t & 15;     // 0..15

    float acc[8][8];
    #pragma unroll
    for (int i = 0; i < 8; ++i)
        #pragma unroll
        for (int j = 0; j < 8; ++j) acc[i][j] = 0.0f;

    for (int kt = 0; kt < GK; kt += 16) {
        #pragma unroll
        for (int v = 0; v < 2; ++v) {
            int idx = t + v * 256;           // 0..511
            int row = idx >> 2;              // 0..127
            int c4  = (idx & 3) * 4;         // 0,4,8,12
            float4 a = *(const float4*)&A[(size_t)(m0 + row) * GK + kt + c4];
            As[c4 + 0][row] = a.x; As[c4 + 1][row] = a.y;
            As[c4 + 2][row] = a.z; As[c4 + 3][row] = a.w;
            float4 w = *(const float4*)&W[(size_t)(n0 + row) * GK + kt + c4];
            Bs[c4 + 0][row] = w.x; Bs[c4 + 1][row] = w.y;
            Bs[c4 + 2][row] = w.z; Bs[c4 + 3][row] = w.w;
        }
        __syncthreads();

        #pragma unroll
        for (int k = 0; k < 16; ++k) {
            float4 a0 = *(const float4*)&As[k][rt * 8];
            float4 a1 = *(const float4*)&As[k][rt * 8 + 4];
            float4 b0 = *(const float4*)&Bs[k][ct * 8];
            float4 b1 = *(const float4*)&Bs[k][ct * 8 + 4];
            float av[8] = {a0.x, a0.y, a0.z, a0.w, a1.x, a1.y, a1.z, a1.w};
            float bv[8] = {b0.x, b0.y, b0.z, b0.w, b1.x, b1.y, b1.z, b1.w};
            #pragma unroll
            for (int i = 0; i < 8; ++i)
                #pragma unroll
                for (int j = 0; j < 8; ++j)
                    acc[i][j] = fmaf(av[i], bv[j], acc[i][j]);
        }
        __syncthreads();
    }

    #pragma unroll
    for (int i = 0; i < 8; ++i) {
        int m = m0 + rt * 8 + i;
        #pragma unroll
        for (int j = 0; j < 8; j += 4) {
            int n = n0 + ct * 8 + j;
            float4 o;
            o.x = acc[i][j + 0] + bias[n + 0];
            o.y = acc[i][j + 1] + bias[n + 1];
            o.z = acc[i][j + 2] + bias[n + 2];
            o.w = acc[i][j + 3] + bias[n + 3];
            *(float4*)&C[(size_t)m * GN + n] = o;
        }
    }
}

// ---------------------------------------------------------------------------
// Persistent recurrent kernel.
// 128 CTAs; CTA c owns output columns j0..j0+7 with its W_h* rows in SMEM.
// Thread t: b = t&63, jq = t>>6 (0..3) -> handles (b, j0+jq) and (b, j0+jq+4).
// Per step: phase A computes r,z (and writes h*r transposed), barrier,
//           phase B computes candidate + h_new, barrier.
// ---------------------------------------------------------------------------
#define SMEM_FLOATS (3 * JPB * HH + CHUNK * BB)
#define SMEM_BYTES  (SMEM_FLOATS * 4)

__global__ __launch_bounds__(RTHREADS, 1) void gru_recurrent(
    const float* __restrict__ state,
    const float* __restrict__ w_hr,
    const float* __restrict__ w_hz,
    const float* __restrict__ w_hh,
    float* __restrict__ out,
    int out_size)
{
    extern __shared__ float smem[];
    float* sW = smem;                    // [3][JPB][HH]
    float* sH = smem + 3 * JPB * HH;     // [CHUNK][BB]

    const int j0 = blockIdx.x * JPB;
    const int t0 = threadIdx.x;

    // Load this CTA's recurrent weight rows into SMEM (resident for all steps)
    {
        const float* Ws[3] = {w_hr, w_hz, w_hh};
        for (int g = 0; g < 3; ++g) {
            for (int idx = t0 * 4; idx < JPB * HH; idx += RTHREADS * 4) {
                int jj = idx / HH;
                int k  = idx - jj * HH;
                float4 v = *(const float4*)&Ws[g][(size_t)(j0 + jj) * HH + k];
                *(float4*)&sW[(size_t)(g * JPB + jj) * HH + k] = v;
            }
        }
    }

    // Initialize transposed h for my column slice: g_hT[j][b] = state[b][j]
    for (int p = t0; p < JPB * BB; p += RTHREADS) {
        int jj = p / BB, b = p % BB;
        g_hT[(size_t)(j0 + jj) * BB + b] = state[(size_t)b * HH + j0 + jj];
    }
    __syncthreads();
    gridBarrier();   // h init + everyone's weights staged

    const int b  = t0 & 63;
    const int jq = t0 >> 6;          // 0..3
    const int jA = j0 + jq;          // first owned column
    const int jB = j0 + jq + 4;      // second owned column

    const float* sWr0 = &sW[(size_t)(0 * JPB + jq    ) * HH];
    const float* sWr1 = &sW[(size_t)(0 * JPB + jq + 4) * HH];
    const float* sWz0 = &sW[(size_t)(1 * JPB + jq    ) * HH];
    const float* sWz1 = &sW[(size_t)(1 * JPB + jq + 4) * HH];
    const float* sWh0 = &sW[(size_t)(2 * JPB + jq    ) * HH];
    const float* sWh1 = &sW[(size_t)(2 * JPB + jq + 4) * HH];

    const float* gatesR = g_gates;
    const float* gatesZ = g_gates + (size_t)1 * TT * BB * HH;
    const float* gatesH = g_gates + (size_t)2 * TT * BB * HH;

    const bool hasFinal = (out_size >= (int64_t)TT * BB * HH + BB * HH);
    float* finalOut = out + (size_t)TT * BB * HH;

    for (int t = 0; t < TT; ++t) {
        const size_t base = ((size_t)t * BB + b) * HH;

        // ---------------- Phase A: r, z ----------------
        float ar0 = 0.f, ar1 = 0.f, az0 = 0.f, az1 = 0.f;
        for (int kc = 0; kc < HH; kc += CHUNK) {
            __syncthreads();
            {
                const float4* src = (const float4*)(g_hT + (size_t)kc * BB);
                float4* dst = (float4*)sH;
                #pragma unroll
                for (int i = t0; i < CHUNK * BB / 4; i += RTHREADS) dst[i] = src[i];
            }
            __syncthreads();
            #pragma unroll 8
            for (int k = 0; k < CHUNK; k += 4) {
                float4 wr0 = *(const float4*)(sWr0 + kc + k);
                float4 wr1 = *(const float4*)(sWr1 + kc + k);
                float4 wz0 = *(const float4*)(sWz0 + kc + k);
                float4 wz1 = *(const float4*)(sWz1 + kc + k);
                float h0 = sH[(k + 0) * BB + b];
                float h1 = sH[(k + 1) * BB + b];
                float h2 = sH[(k + 2) * BB + b];
                float h3 = sH[(k + 3) * BB + b];
                ar0 = fmaf(h0, wr0.x, ar0); ar0 = fmaf(h1, wr0.y, ar0);
                ar0 = fmaf(h2, wr0.z, ar0); ar0 = fmaf(h3, wr0.w, ar0);
                ar1 = fmaf(h0, wr1.x, ar1); ar1 = fmaf(h1, wr1.y, ar1);
                ar1 = fmaf(h2, wr1.z, ar1); ar1 = fmaf(h3, wr1.w, ar1);
                az0 = fmaf(h0, wz0.x, az0); az0 = fmaf(h1, wz0.y, az0);
                az0 = fmaf(h2, wz0.z, az0); az0 = fmaf(h3, wz0.w, az0);
                az1 = fmaf(h0, wz1.x, az1); az1 = fmaf(h1, wz1.y, az1);
                az1 = fmaf(h2, wz1.z, az1); az1 = fmaf(h3, wz1.w, az1);
            }
        }

        float r0 = sigmoidf_(gatesR[base + jA] + ar0);
        float r1 = sigmoidf_(gatesR[base + jB] + ar1);
        float z0 = sigmoidf_(gatesZ[base + jA] + az0);
        float z1 = sigmoidf_(gatesZ[base + jB] + az1);

        float hold0 = g_hT[(size_t)jA * BB + b];
        float hold1 = g_hT[(size_t)jB * BB + b];
        g_hrT[(size_t)jA * BB + b] = hold0 * r0;
        g_hrT[(size_t)jB * BB + b] = hold1 * r1;

        gridBarrier();   // hr fully published

        // ---------------- Phase B: candidate + h_new ----------------
        float ah0 = 0.f, ah1 = 0.f;
        for (int kc = 0; kc < HH; kc += CHUNK) {
            __syncthreads();
            {
                const float4* src = (const float4*)(g_hrT + (size_t)kc * BB);
                float4* dst = (float4*)sH;
                #pragma unroll
                for (int i = t0; i < CHUNK * BB / 4; i += RTHREADS) dst[i] = src[i];
            }
            __syncthreads();
            #pragma unroll 8
            for (int k = 0; k < CHUNK; k += 4) {
                float4 wh0 = *(const float4*)(sWh0 + kc + k);
                float4 wh1 = *(const float4*)(sWh1 + kc + k);
                float h0 = sH[(k + 0) * BB + b];
                float h1 = sH[(k + 1) * BB + b];
                float h2 = sH[(k + 2) * BB + b];
                float h3 = sH[(k + 3) * BB + b];
                ah0 = fmaf(h0, wh0.x, ah0); ah0 = fmaf(h1, wh0.y, ah0);
                ah0 = fmaf(h2, wh0.z, ah0); ah0 = fmaf(h3, wh0.w, ah0);
                ah1 = fmaf(h0, wh1.x, ah1); ah1 = fmaf(h1, wh1.y, ah1);
                ah1 = fmaf(h2, wh1.z, ah1); ah1 = fmaf(h3, wh1.w, ah1);
            }
        }

        float c0 = tanhf(gatesH[base + jA] + ah0);
        float c1 = tanhf(gatesH[base + jB] + ah1);
        float hn0 = z0 * hold0 + (1.0f - z0) * c0;
        float hn1 = z1 * hold1 + (1.0f - z1) * c1;

        g_hT[(size_t)jA * BB + b] = hn0;
        g_hT[(size_t)jB * BB + b] = hn1;
        out[base + jA] = hn0;
        out[base + jB] = hn1;
        if (hasFinal && t == TT - 1) {
            finalOut[(size_t)b * HH + jA] = hn0;
            finalOut[(size_t)b * HH + jB] = hn1;
        }

        gridBarrier();   // new h fully published before next step
    }
}

// ---------------------------------------------------------------------------
// kernel_launch: inputs in metadata order:
// 0:x 1:state 2:w_xr_w 3:w_xr_b 4:w_hr_w 5:w_xz_w 6:w_xz_b 7:w_hz_w
// 8:w_xh_w 9:w_xh_b 10:w_hh_w
// ---------------------------------------------------------------------------
extern "C" void kernel_launch(void* const* d_in, const int* in_sizes, int n_in,
                              void* d_out, int out_size)
{
    const float* x      = (const float*)d_in[0];
    const float* state  = (const float*)d_in[1];
    const float* w_xr_w = (const float*)d_in[2];
    const float* w_xr_b = (const float*)d_in[3];
    const float* w_hr_w = (const float*)d_in[4];
    const float* w_xz_w = (const float*)d_in[5];
    const float* w_xz_b = (const float*)d_in[6];
    const float* w_hz_w = (const float*)d_in[7];
    const float* w_xh_w = (const float*)d_in[8];
    const float* w_xh_b = (const float*)d_in[9];
    const float* w_hh_w = (const float*)d_in[10];

    cudaFuncSetAttribute(gru_recurrent,
                         cudaFuncAttributeMaxDynamicSharedMemorySize, SMEM_BYTES);

    dim3 gg(GN / 128, GM / 128);
    sgemm_gate<<<gg, 256>>>(x, w_xr_w, w_xr_b, 0);
    sgemm_gate<<<gg, 256>>>(x, w_xz_w, w_xz_b, 1);
    sgemm_gate<<<gg, 256>>>(x, w_xh_w, w_xh_b, 2);

    gru_recurrent<<<NBLK, RTHREADS, SMEM_BYTES>>>(
        state, w_hr_w, w_hz_w, w_hh_w, (float*)d_out, out_size);
}

// round 2
// speedup vs baseline: 1.1030x; 1.1030x over previous
#include <cuda_runtime.h>
#include <cuda_bf16.h>
#include <cstdint>

// Problem constants
#define TT 512
#define BB 64
#define II 1024
#define HH 1024
#define GM (TT*BB)     // 32768 rows of the input GEMM
#define GK II
#define GN HH

// Recurrent kernel config
#define NBLK 128       // persistent CTAs (<= 148 SMs, all resident)
#define JPB  8         // output columns per CTA (128*8 = 1024)
#define RTHREADS 256
#define CHUNK 256      // k-chunk of h staged in smem

// Scratch (static __device__ allocations only; no cudaMalloc allowed)
__device__ float g_gates[(size_t)3 * TT * BB * HH];  // xr/xz/xh pre-projections
__device__ float g_hT [(size_t)HH * BB];             // h transposed [j][b]
__device__ float g_hrT[(size_t)HH * BB];             // (h*reset) transposed [j][b]
__device__ unsigned g_bar_cnt;
__device__ unsigned g_bar_gen;

// ---------------------------------------------------------------------------
// Grid-wide barrier (all NBLK CTAs co-resident: grid <= SM count, 1 CTA/SM)
// ---------------------------------------------------------------------------
__device__ __forceinline__ void gridBarrier() {
    __syncthreads();
    if (threadIdx.x == 0) {
        __threadfence();                       // publish my writes
        volatile unsigned* vgen = &g_bar_gen;
        unsigned gen = *vgen;                  // read epoch BEFORE arriving
        if (atomicAdd(&g_bar_cnt, 1u) == NBLK - 1u) {
            g_bar_cnt = 0u;
            __threadfence();
            *vgen = gen + 1u;                  // release
        } else {
            while (*vgen == gen) { __nanosleep(32); }
        }
        __threadfence();                       // acquire others' writes
    }
    __syncthreads();
}

__device__ __forceinline__ float sigmoidf_(float x) {
    return 1.0f / (1.0f + __expf(-x));
}

__device__ __forceinline__ uint32_t f2tf32(float x) {
    uint32_t r;
    asm("cvt.rna.tf32.f32 %0, %1;" : "=r"(r) : "f"(x));
    return r;
}

// ---------------------------------------------------------------------------
// TF32 tensor-core input projection GEMM.
// C[m,n] = sum_k A[m,k] * W[n,k] + bias[n]
// A = x flattened [GM,GK] row-major, W = [GN,GK] row-major.
// CTA tile 128x128, BK=32. 8 warps, warp tile 64x32 (4x4 m16n8k8 atoms).
// SMEM stores tf32-converted tiles k-major with stride 136 (conflict-free
// fragment gathers: bank = (8*t + g) over lanes).
// gridDim.z = gate (0:r, 1:z, 2:h).
// ---------------------------------------------------------------------------
#define BKT 32
#define SASTRIDE 136   // 128 + 8 pad

__global__ __launch_bounds__(256) void mma_gate(
    const float* __restrict__ A,
    const float* __restrict__ W0, const float* __restrict__ W1, const float* __restrict__ W2,
    const float* __restrict__ b0, const float* __restrict__ b1, const float* __restrict__ b2)
{
    __shared__ uint32_t As[BKT * SASTRIDE];
    __shared__ uint32_t Ws[BKT * SASTRIDE];

    const int gate = blockIdx.z;
    const float* W    = (gate == 0) ? W0 : (gate == 1) ? W1 : W2;
    const float* bias = (gate == 0) ? b0 : (gate == 1) ? b1 : b2;
    float* C = g_gates + (size_t)gate * GM * GN;

    const int m0 = blockIdx.y * 128;
    const int n0 = blockIdx.x * 128;
    const int tid  = threadIdx.x;
    const int wid  = tid >> 5;
    const int lane = tid & 31;
    const int g  = lane >> 2;     // 0..7
    const int t4 = lane & 3;      // 0..3

    const int wm = (wid & 1) * 64;   // warp m-offset within CTA tile
    const int wn = (wid >> 1) * 32;  // warp n-offset

    float acc[4][4][4];
    #pragma unroll
    for (int mi = 0; mi < 4; ++mi)
        #pragma unroll
        for (int ni = 0; ni < 4; ++ni)
            #pragma unroll
            for (int r = 0; r < 4; ++r) acc[mi][ni][r] = 0.0f;

    for (int kt = 0; kt < GK; kt += BKT) {
        // Stage tiles (converted to tf32), layout [k][m]/[k][n] stride 136.
        #pragma unroll
        for (int i = 0; i < 4; ++i) {
            int idx = tid + i * 256;          // 0..1023 (float4 units)
            int row = idx >> 3;               // 0..127
            int kc4 = (idx & 7) * 4;          // 0,4,...,28
            float4 a = *(const float4*)&A[(size_t)(m0 + row) * GK + kt + kc4];
            As[(kc4 + 0) * SASTRIDE + row] = f2tf32(a.x);
            As[(kc4 + 1) * SASTRIDE + row] = f2tf32(a.y);
            As[(kc4 + 2) * SASTRIDE + row] = f2tf32(a.z);
            As[(kc4 + 3) * SASTRIDE + row] = f2tf32(a.w);
            float4 w = *(const float4*)&W[(size_t)(n0 + row) * GK + kt + kc4];
            Ws[(kc4 + 0) * SASTRIDE + row] = f2tf32(w.x);
            Ws[(kc4 + 1) * SASTRIDE + row] = f2tf32(w.y);
            Ws[(kc4 + 2) * SASTRIDE + row] = f2tf32(w.z);
            Ws[(kc4 + 3) * SASTRIDE + row] = f2tf32(w.w);
        }
        __syncthreads();

        #pragma unroll
        for (int ks = 0; ks < BKT; ks += 8) {
            uint32_t af[4][4];
            #pragma unroll
            for (int mi = 0; mi < 4; ++mi) {
                int m = wm + mi * 16 + g;
                af[mi][0] = As[(ks + t4    ) * SASTRIDE + m    ];
                af[mi][1] = As[(ks + t4    ) * SASTRIDE + m + 8];
                af[mi][2] = As[(ks + t4 + 4) * SASTRIDE + m    ];
                af[mi][3] = As[(ks + t4 + 4) * SASTRIDE + m + 8];
            }
            uint32_t bf[4][2];
            #pragma unroll
            for (int ni = 0; ni < 4; ++ni) {
                int n = wn + ni * 8 + g;
                bf[ni][0] = Ws[(ks + t4    ) * SASTRIDE + n];
                bf[ni][1] = Ws[(ks + t4 + 4) * SASTRIDE + n];
            }
            #pragma unroll
            for (int mi = 0; mi < 4; ++mi)
                #pragma unroll
                for (int ni = 0; ni < 4; ++ni) {
                    asm volatile(
                        "mma.sync.aligned.m16n8k8.row.col.f32.tf32.tf32.f32 "
                        "{%0,%1,%2,%3}, {%4,%5,%6,%7}, {%8,%9}, {%0,%1,%2,%3};"
                        : "+f"(acc[mi][ni][0]), "+f"(acc[mi][ni][1]),
                          "+f"(acc[mi][ni][2]), "+f"(acc[mi][ni][3])
                        : "r"(af[mi][0]), "r"(af[mi][1]), "r"(af[mi][2]), "r"(af[mi][3]),
                          "r"(bf[ni][0]), "r"(bf[ni][1]));
                }
        }
        __syncthreads();
    }

    // Epilogue: c0,c1 -> (row g, cols 2t,2t+1); c2,c3 -> row g+8.
    #pragma unroll
    for (int mi = 0; mi < 4; ++mi) {
        int mrow = m0 + wm + mi * 16 + g;
        #pragma unroll
        for (int ni = 0; ni < 4; ++ni) {
            int col = n0 + wn + ni * 8 + 2 * t4;
            float bx = bias[col], by = bias[col + 1];
            float2 o0 = make_float2(acc[mi][ni][0] + bx, acc[mi][ni][1] + by);
            float2 o1 = make_float2(acc[mi][ni][2] + bx, acc[mi][ni][3] + by);
            *(float2*)&C[(size_t)mrow * GN + col] = o0;
            *(float2*)&C[(size_t)(mrow + 8) * GN + col] = o1;
        }
    }
}

// ---------------------------------------------------------------------------
// Persistent recurrent kernel (unchanged from R1 — near its fp32 SIMT floor;
// tensor-core rewrite is the next-round candidate once GEMM delta is known).
// ---------------------------------------------------------------------------
#define SMEM_FLOATS (3 * JPB * HH + CHUNK * BB)
#define SMEM_BYTES  (SMEM_FLOATS * 4)

__global__ __launch_bounds__(RTHREADS, 1) void gru_recurrent(
    const float* __restrict__ state,
    const float* __restrict__ w_hr,
    const float* __restrict__ w_hz,
    const float* __restrict__ w_hh,
    float* __restrict__ out,
    int out_size)
{
    extern __shared__ float smem[];
    float* sW = smem;                    // [3][JPB][HH]
    float* sH = smem + 3 * JPB * HH;     // [CHUNK][BB]

    const int j0 = blockIdx.x * JPB;
    const int t0 = threadIdx.x;

    {
        const float* Ws3[3] = {w_hr, w_hz, w_hh};
        for (int gg = 0; gg < 3; ++gg) {
            for (int idx = t0 * 4; idx < JPB * HH; idx += RTHREADS * 4) {
                int jj = idx / HH;
                int k  = idx - jj * HH;
                float4 v = *(const float4*)&Ws3[gg][(size_t)(j0 + jj) * HH + k];
                *(float4*)&sW[(size_t)(gg * JPB + jj) * HH + k] = v;
            }
        }
    }

    for (int p = t0; p < JPB * BB; p += RTHREADS) {
        int jj = p / BB, b = p % BB;
        g_hT[(size_t)(j0 + jj) * BB + b] = state[(size_t)b * HH + j0 + jj];
    }
    __syncthreads();
    gridBarrier();

    const int b  = t0 & 63;
    const int jq = t0 >> 6;
    const int jA = j0 + jq;
    const int jB = j0 + jq + 4;

    const float* sWr0 = &sW[(size_t)(0 * JPB + jq    ) * HH];
    const float* sWr1 = &sW[(size_t)(0 * JPB + jq + 4) * HH];
    const float* sWz0 = &sW[(size_t)(1 * JPB + jq    ) * HH];
    const float* sWz1 = &sW[(size_t)(1 * JPB + jq + 4) * HH];
    const float* sWh0 = &sW[(size_t)(2 * JPB + jq    ) * HH];
    const float* sWh1 = &sW[(size_t)(2 * JPB + jq + 4) * HH];

    const float* gatesR = g_gates;
    const float* gatesZ = g_gates + (size_t)1 * TT * BB * HH;
    const float* gatesH = g_gates + (size_t)2 * TT * BB * HH;

    const bool hasFinal = (out_size >= (int64_t)TT * BB * HH + BB * HH);
    float* finalOut = out + (size_t)TT * BB * HH;

    for (int t = 0; t < TT; ++t) {
        const size_t base = ((size_t)t * BB + b) * HH;

        float ar0 = 0.f, ar1 = 0.f, az0 = 0.f, az1 = 0.f;
        for (int kc = 0; kc < HH; kc += CHUNK) {
            __syncthreads();
            {
                const float4* src = (const float4*)(g_hT + (size_t)kc * BB);
                float4* dst = (float4*)sH;
                #pragma unroll
                for (int i = t0; i < CHUNK * BB / 4; i += RTHREADS) dst[i] = src[i];
            }
            __syncthreads();
            #pragma unroll 8
            for (int k = 0; k < CHUNK; k += 4) {
                float4 wr0 = *(const float4*)(sWr0 + kc + k);
                float4 wr1 = *(const float4*)(sWr1 + kc + k);
                float4 wz0 = *(const float4*)(sWz0 + kc + k);
                float4 wz1 = *(const float4*)(sWz1 + kc + k);
                float h0 = sH[(k + 0) * BB + b];
                float h1 = sH[(k + 1) * BB + b];
                float h2 = sH[(k + 2) * BB + b];
                float h3 = sH[(k + 3) * BB + b];
                ar0 = fmaf(h0, wr0.x, ar0); ar0 = fmaf(h1, wr0.y, ar0);
                ar0 = fmaf(h2, wr0.z, ar0); ar0 = fmaf(h3, wr0.w, ar0);
                ar1 = fmaf(h0, wr1.x, ar1); ar1 = fmaf(h1, wr1.y, ar1);
                ar1 = fmaf(h2, wr1.z, ar1); ar1 = fmaf(h3, wr1.w, ar1);
                az0 = fmaf(h0, wz0.x, az0); az0 = fmaf(h1, wz0.y, az0);
                az0 = fmaf(h2, wz0.z, az0); az0 = fmaf(h3, wz0.w, az0);
                az1 = fmaf(h0, wz1.x, az1); az1 = fmaf(h1, wz1.y, az1);
                az1 = fmaf(h2, wz1.z, az1); az1 = fmaf(h3, wz1.w, az1);
            }
        }

        float r0 = sigmoidf_(gatesR[base + jA] + ar0);
        float r1 = sigmoidf_(gatesR[base + jB] + ar1);
        float z0 = sigmoidf_(gatesZ[base + jA] + az0);
        float z1 = sigmoidf_(gatesZ[base + jB] + az1);

        float hold0 = g_hT[(size_t)jA * BB + b];
        float hold1 = g_hT[(size_t)jB * BB + b];
        g_hrT[(size_t)jA * BB + b] = hold0 * r0;
        g_hrT[(size_t)jB * BB + b] = hold1 * r1;

        gridBarrier();

        float ah0 = 0.f, ah1 = 0.f;
        for (int kc = 0; kc < HH; kc += CHUNK) {
            __syncthreads();
            {
                const float4* src = (const float4*)(g_hrT + (size_t)kc * BB);
                float4* dst = (float4*)sH;
                #pragma unroll
                for (int i = t0; i < CHUNK * BB / 4; i += RTHREADS) dst[i] = src[i];
            }
            __syncthreads();
            #pragma unroll 8
            for (int k = 0; k < CHUNK; k += 4) {
                float4 wh0 = *(const float4*)(sWh0 + kc + k);
                float4 wh1 = *(const float4*)(sWh1 + kc + k);
                float h0 = sH[(k + 0) * BB + b];
                float h1 = sH[(k + 1) * BB + b];
                float h2 = sH[(k + 2) * BB + b];
                float h3 = sH[(k + 3) * BB + b];
                ah0 = fmaf(h0, wh0.x, ah0); ah0 = fmaf(h1, wh0.y, ah0);
                ah0 = fmaf(h2, wh0.z, ah0); ah0 = fmaf(h3, wh0.w, ah0);
                ah1 = fmaf(h0, wh1.x, ah1); ah1 = fmaf(h1, wh1.y, ah1);
                ah1 = fmaf(h2, wh1.z, ah1); ah1 = fmaf(h3, wh1.w, ah1);
            }
        }

        float c0 = tanhf(gatesH[base + jA] + ah0);
        float c1 = tanhf(gatesH[base + jB] + ah1);
        float hn0 = z0 * hold0 + (1.0f - z0) * c0;
        float hn1 = z1 * hold1 + (1.0f - z1) * c1;

        g_hT[(size_t)jA * BB + b] = hn0;
        g_hT[(size_t)jB * BB + b] = hn1;
        out[base + jA] = hn0;
        out[base + jB] = hn1;
        if (hasFinal && t == TT - 1) {
            finalOut[(size_t)b * HH + jA] = hn0;
            finalOut[(size_t)b * HH + jB] = hn1;
        }

        gridBarrier();
    }
}

// ---------------------------------------------------------------------------
// kernel_launch: inputs in metadata order:
// 0:x 1:state 2:w_xr_w 3:w_xr_b 4:w_hr_w 5:w_xz_w 6:w_xz_b 7:w_hz_w
// 8:w_xh_w 9:w_xh_b 10:w_hh_w
// ---------------------------------------------------------------------------
extern "C" void kernel_launch(void* const* d_in, const int* in_sizes, int n_in,
                              void* d_out, int out_size)
{
    const float* x      = (const float*)d_in[0];
    const float* state  = (const float*)d_in[1];
    const float* w_xr_w = (const float*)d_in[2];
    const float* w_xr_b = (const float*)d_in[3];
    const float* w_hr_w = (const float*)d_in[4];
    const float* w_xz_w = (const float*)d_in[5];
    const float* w_xz_b = (const float*)d_in[6];
    const float* w_hz_w = (const float*)d_in[7];
    const float* w_xh_w = (const float*)d_in[8];
    const float* w_xh_b = (const float*)d_in[9];
    const float* w_hh_w = (const float*)d_in[10];

    cudaFuncSetAttribute(gru_recurrent,
                         cudaFuncAttributeMaxDynamicSharedMemorySize, SMEM_BYTES);

    dim3 gg(GN / 128, GM / 128, 3);
    mma_gate<<<gg, 256>>>(x, w_xr_w, w_xz_w, w_xh_w, w_xr_b, w_xz_b, w_xh_b);

    gru_recurrent<<<NBLK, RTHREADS, SMEM_BYTES>>>(
        state, w_hr_w, w_hz_w, w_hh_w, (float*)d_out, out_size);
}

// round 3
// speedup vs baseline: 1.3880x; 1.2583x over previous
#include <cuda_runtime.h>
#include <cuda_bf16.h>
#include <cstdint>

// Problem constants
#define TT 512
#define BB 64
#define II 1024
#define HH 1024
#define GM (TT*BB)
#define GK II
#define GN HH

// Recurrent kernel config
#define NBLK 128
#define JPB  8
#define RTHREADS 256
#define HSTR 264          // h chunk smem stride (floats), 264 % 32 == 8 -> conflict-free frags
#define RCHUNK 256        // k-chunk of h staged per iteration

// Scratch
__device__ float g_gates[(size_t)3 * TT * BB * HH];
__device__ float g_h [(size_t)BB * HH];     // h, layout [b][k]
__device__ float g_hr[(size_t)BB * HH];     // h*reset, layout [b][k]
__device__ unsigned g_bar_cnt;
__device__ unsigned g_bar_gen;

// ---------------------------------------------------------------------------
__device__ __forceinline__ void gridBarrier() {
    __syncthreads();
    if (threadIdx.x == 0) {
        __threadfence();
        volatile unsigned* vgen = &g_bar_gen;
        unsigned gen = *vgen;
        if (atomicAdd(&g_bar_cnt, 1u) == NBLK - 1u) {
            g_bar_cnt = 0u;
            __threadfence();
            *vgen = gen + 1u;
        } else {
            while (*vgen == gen) { __nanosleep(32); }
        }
        __threadfence();
    }
    __syncthreads();
}

__device__ __forceinline__ float sigmoidf_(float x) {
    return 1.0f / (1.0f + __expf(-x));
}

__device__ __forceinline__ uint32_t f2tf32(float x) {
    uint32_t r;
    asm("cvt.rna.tf32.f32 %0, %1;" : "=r"(r) : "f"(x));
    return r;
}

__device__ __forceinline__ void mma_tf32(float acc[4],
                                         uint32_t a0, uint32_t a1, uint32_t a2, uint32_t a3,
                                         uint32_t b0, uint32_t b1) {
    asm volatile(
        "mma.sync.aligned.m16n8k8.row.col.f32.tf32.tf32.f32 "
        "{%0,%1,%2,%3}, {%4,%5,%6,%7}, {%8,%9}, {%0,%1,%2,%3};"
        : "+f"(acc[0]), "+f"(acc[1]), "+f"(acc[2]), "+f"(acc[3])
        : "r"(a0), "r"(a1), "r"(a2), "r"(a3), "r"(b0), "r"(b1));
}

// ---------------------------------------------------------------------------
// TF32 input projection GEMM (unchanged from R2, ~2ms)
// ---------------------------------------------------------------------------
#define BKT 32
#define SASTRIDE 136

__global__ __launch_bounds__(256) void mma_gate(
    const float* __restrict__ A,
    const float* __restrict__ W0, const float* __restrict__ W1, const float* __restrict__ W2,
    const float* __restrict__ b0, const float* __restrict__ b1, const float* __restrict__ b2)
{
    __shared__ uint32_t As[BKT * SASTRIDE];
    __shared__ uint32_t Ws[BKT * SASTRIDE];

    const int gate = blockIdx.z;
    const float* W    = (gate == 0) ? W0 : (gate == 1) ? W1 : W2;
    const float* bias = (gate == 0) ? b0 : (gate == 1) ? b1 : b2;
    float* C = g_gates + (size_t)gate * GM * GN;

    const int m0 = blockIdx.y * 128;
    const int n0 = blockIdx.x * 128;
    const int tid  = threadIdx.x;
    const int wid  = tid >> 5;
    const int lane = tid & 31;
    const int g  = lane >> 2;
    const int t4 = lane & 3;

    const int wm = (wid & 1) * 64;
    const int wn = (wid >> 1) * 32;

    float acc[4][4][4];
    #pragma unroll
    for (int mi = 0; mi < 4; ++mi)
        #pragma unroll
        for (int ni = 0; ni < 4; ++ni)
            #pragma unroll
            for (int r = 0; r < 4; ++r) acc[mi][ni][r] = 0.0f;

    for (int kt = 0; kt < GK; kt += BKT) {
        #pragma unroll
        for (int i = 0; i < 4; ++i) {
            int idx = tid + i * 256;
            int row = idx >> 3;
            int kc4 = (idx & 7) * 4;
            float4 a = *(const float4*)&A[(size_t)(m0 + row) * GK + kt + kc4];
            As[(kc4 + 0) * SASTRIDE + row] = f2tf32(a.x);
            As[(kc4 + 1) * SASTRIDE + row] = f2tf32(a.y);
            As[(kc4 + 2) * SASTRIDE + row] = f2tf32(a.z);
            As[(kc4 + 3) * SASTRIDE + row] = f2tf32(a.w);
            float4 w = *(const float4*)&W[(size_t)(n0 + row) * GK + kt + kc4];
            Ws[(kc4 + 0) * SASTRIDE + row] = f2tf32(w.x);
            Ws[(kc4 + 1) * SASTRIDE + row] = f2tf32(w.y);
            Ws[(kc4 + 2) * SASTRIDE + row] = f2tf32(w.z);
            Ws[(kc4 + 3) * SASTRIDE + row] = f2tf32(w.w);
        }
        __syncthreads();

        #pragma unroll
        for (int ks = 0; ks < BKT; ks += 8) {
            uint32_t af[4][4];
            #pragma unroll
            for (int mi = 0; mi < 4; ++mi) {
                int m = wm + mi * 16 + g;
                af[mi][0] = As[(ks + t4    ) * SASTRIDE + m    ];
                af[mi][1] = As[(ks + t4    ) * SASTRIDE + m + 8];
                af[mi][2] = As[(ks + t4 + 4) * SASTRIDE + m    ];
                af[mi][3] = As[(ks + t4 + 4) * SASTRIDE + m + 8];
            }
            uint32_t bf[4][2];
            #pragma unroll
            for (int ni = 0; ni < 4; ++ni) {
                int n = wn + ni * 8 + g;
                bf[ni][0] = Ws[(ks + t4    ) * SASTRIDE + n];
                bf[ni][1] = Ws[(ks + t4 + 4) * SASTRIDE + n];
            }
            #pragma unroll
            for (int mi = 0; mi < 4; ++mi)
                #pragma unroll
                for (int ni = 0; ni < 4; ++ni)
                    mma_tf32(acc[mi][ni], af[mi][0], af[mi][1], af[mi][2], af[mi][3],
                             bf[ni][0], bf[ni][1]);
        }
        __syncthreads();
    }

    #pragma unroll
    for (int mi = 0; mi < 4; ++mi) {
        int mrow = m0 + wm + mi * 16 + g;
        #pragma unroll
        for (int ni = 0; ni < 4; ++ni) {
            int col = n0 + wn + ni * 8 + 2 * t4;
            float bx = bias[col], by = bias[col + 1];
            float2 o0 = make_float2(acc[mi][ni][0] + bx, acc[mi][ni][1] + by);
            float2 o1 = make_float2(acc[mi][ni][2] + bx, acc[mi][ni][3] + by);
            *(float2*)&C[(size_t)mrow * GN + col] = o0;
            *(float2*)&C[(size_t)(mrow + 8) * GN + col] = o1;
        }
    }
}

// ---------------------------------------------------------------------------
// Tensor-core persistent recurrent kernel.
// 128 CTAs x 8 cols. Weights pre-swizzled to tf32 B-fragment order in smem.
// Phase A: 8 warps = 4(m: batch16) x 2(gate r/z), each m16n8, K=1024 (128 MMAs).
// Phase B: 8 warps = 4(m) x 2(k-half), each m16n8 K=512, smem reduce.
// h / h*r live in global [b][k]; staged per 256-k chunk as tf32 into smem.
// ---------------------------------------------------------------------------
// Shared layout (bytes):
#define OFF_WF   0
#define SZ_WF    (3 * 128 * 32 * 8)            // uint2 [3][128][32] = 98304
#define OFF_SH   (OFF_WF + SZ_WF)
#define SZ_SH    (BB * HSTR * 4)               // 67584
#define OFF_SZ   (OFF_SH + SZ_SH)
#define SZ_SZ    (BB * JPB * 4)                // 2048
#define OFF_SHO  (OFF_SZ + SZ_SZ)
#define SZ_SHO   (BB * JPB * 4)
#define OFF_SRED (OFF_SHO + SZ_SHO)
#define SZ_SRED  (4 * 32 * 4 * 4)              // 2048
#define RSMEM_BYTES (OFF_SRED + SZ_SRED)       // ~172KB

__device__ __forceinline__ void stageChunk(uint32_t* sH, const float* __restrict__ src,
                                           int kc, int tid) {
    #pragma unroll 4
    for (int i = tid; i < BB * (RCHUNK / 4); i += RTHREADS) {
        int b  = i >> 6;               // RCHUNK/4 = 64 float4 per row
        int c4 = (i & 63) << 2;
        float4 v = *(const float4*)&src[(size_t)b * HH + kc + c4];
        uint4 u;
        u.x = f2tf32(v.x); u.y = f2tf32(v.y); u.z = f2tf32(v.z); u.w = f2tf32(v.w);
        *(uint4*)&sH[b * HSTR + c4] = u;
    }
}

__global__ __launch_bounds__(RTHREADS, 1) void gru_recurrent(
    const float* __restrict__ state,
    const float* __restrict__ w_hr,
    const float* __restrict__ w_hz,
    const float* __restrict__ w_hh,
    float* __restrict__ out,
    int out_size)
{
    extern __shared__ char smem[];
    uint2*    uWf   = (uint2*)(smem + OFF_WF);     // [g3][kk8][lane]
    uint32_t* sH    = (uint32_t*)(smem + OFF_SH);  // staged h chunk (tf32 bits)
    float*    sZ    = (float*)(smem + OFF_SZ);     // z[b][jj]
    float*    sHold = (float*)(smem + OFF_SHO);    // h_old[b][jj]
    float*    sRed  = (float*)(smem + OFF_SRED);   // phase-B k-split partials

    const int j0  = blockIdx.x * JPB;
    const int tid = threadIdx.x;
    const int wid = tid >> 5;
    const int lane = tid & 31;
    const int g  = lane >> 2;     // 0..7
    const int t4 = lane & 3;      // 0..3

    // ---- Prep: weights -> tf32 fragment order (once) ----
    {
        const float* Ws3[3] = {w_hr, w_hz, w_hh};
        for (int g3 = 0; g3 < 3; ++g3) {
            const float* W = Ws3[g3];
            for (int idx = tid; idx < 128 * 32; idx += RTHREADS) {
                int kk8 = idx >> 5;
                int ln  = idx & 31;
                int jj  = ln >> 2;
                int kk  = (kk8 << 3) + (ln & 3);
                uint2 v;
                v.x = f2tf32(W[(size_t)(j0 + jj) * HH + kk]);
                v.y = f2tf32(W[(size_t)(j0 + jj) * HH + kk + 4]);
                uWf[(g3 * 128 + kk8) * 32 + ln] = v;
            }
        }
    }

    // ---- Init h for my columns ----
    for (int p = tid; p < BB * JPB; p += RTHREADS) {
        int b = p >> 3, jj = p & 7;
        g_h[(size_t)b * HH + j0 + jj] = state[(size_t)b * HH + j0 + jj];
    }
    gridBarrier();

    const float* gatesR = g_gates;
    const float* gatesZ = g_gates + (size_t)1 * TT * BB * HH;
    const float* gatesH = g_gates + (size_t)2 * TT * BB * HH;
    const bool hasFinal = (out_size >= (int)((size_t)TT * BB * HH + BB * HH));
    float* finalOut = out + (size_t)TT * BB * HH;

    // Phase A role
    const int miA = wid & 3;         // batch tile
    const int niA = wid >> 2;        // 0 = r gate, 1 = z gate
    const int m0A = miA * 16;
    // Phase B role
    const int miB = wid & 3;
    const int khB = wid >> 2;        // k half

    const int bR0 = g;               // rows within m-tile: g and g+8
    const int jA2 = 2 * t4;          // cols within n8: 2t4, 2t4+1

    for (int t = 0; t < TT; ++t) {
        const size_t baseT = (size_t)t * BB * HH;

        // ================= Phase A: r and z =================
        float acc[4] = {0.f, 0.f, 0.f, 0.f};
        #pragma unroll 1
        for (int kc = 0; kc < HH; kc += RCHUNK) {
            __syncthreads();
            stageChunk(sH, g_h, kc, tid);
            __syncthreads();
            const uint2* wf = &uWf[(niA * 128 + (kc >> 3)) * 32 + lane];
            const uint32_t* hp0 = &sH[(m0A + g) * HSTR + t4];
            const uint32_t* hp1 = &sH[(m0A + g + 8) * HSTR + t4];
            #pragma unroll 8
            for (int kk = 0; kk < RCHUNK / 8; ++kk) {
                uint32_t a0 = hp0[kk * 8];
                uint32_t a1 = hp1[kk * 8];
                uint32_t a2 = hp0[kk * 8 + 4];
                uint32_t a3 = hp1[kk * 8 + 4];
                uint2 b2 = wf[kk * 32];
                mma_tf32(acc, a0, a1, a2, a3, b2.x, b2.y);
            }
        }

        // Epilogue A: thread holds (b0,jA),(b0,jA+1),(b1,jA),(b1,jA+1)
        {
            int b0 = m0A + bR0, b1 = b0 + 8;
            int jc = j0 + jA2;
            if (niA == 0) {   // reset gate -> write g_hr, stash h_old
                float2 gr0 = *(const float2*)&gatesR[baseT + (size_t)b0 * HH + jc];
                float2 gr1 = *(const float2*)&gatesR[baseT + (size_t)b1 * HH + jc];
                float r00 = sigmoidf_(gr0.x + acc[0]);
                float r01 = sigmoidf_(gr0.y + acc[1]);
                float r10 = sigmoidf_(gr1.x + acc[2]);
                float r11 = sigmoidf_(gr1.y + acc[3]);
                float2 h0 = *(const float2*)&g_h[(size_t)b0 * HH + jc];
                float2 h1 = *(const float2*)&g_h[(size_t)b1 * HH + jc];
                *(float2*)&g_hr[(size_t)b0 * HH + jc] = make_float2(h0.x * r00, h0.y * r01);
                *(float2*)&g_hr[(size_t)b1 * HH + jc] = make_float2(h1.x * r10, h1.y * r11);
                *(float2*)&sHold[b0 * JPB + jA2] = h0;
                *(float2*)&sHold[b1 * JPB + jA2] = h1;
            } else {          // update gate -> stash z
                float2 gz0 = *(const float2*)&gatesZ[baseT + (size_t)b0 * HH + jc];
                float2 gz1 = *(const float2*)&gatesZ[baseT + (size_t)b1 * HH + jc];
                *(float2*)&sZ[b0 * JPB + jA2] =
                    make_float2(sigmoidf_(gz0.x + acc[0]), sigmoidf_(gz0.y + acc[1]));
                *(float2*)&sZ[b1 * JPB + jA2] =
                    make_float2(sigmoidf_(gz1.x + acc[2]), sigmoidf_(gz1.y + acc[3]));
            }
        }

        gridBarrier();   // all hr published

        // ================= Phase B: candidate =================
        float accB[4] = {0.f, 0.f, 0.f, 0.f};
        #pragma unroll 1
        for (int c = 0; c < 4; ++c) {
            int kc = c * RCHUNK;
            __syncthreads();
            stageChunk(sH, g_hr, kc, tid);
            __syncthreads();
            if ((c >> 1) == khB) {
                const uint2* wf = &uWf[(2 * 128 + (kc >> 3)) * 32 + lane];
                const uint32_t* hp0 = &sH[(miB * 16 + g) * HSTR + t4];
                const uint32_t* hp1 = &sH[(miB * 16 + g + 8) * HSTR + t4];
                #pragma unroll 8
                for (int kk = 0; kk < RCHUNK / 8; ++kk) {
                    uint32_t a0 = hp0[kk * 8];
                    uint32_t a1 = hp1[kk * 8];
                    uint32_t a2 = hp0[kk * 8 + 4];
                    uint32_t a3 = hp1[kk * 8 + 4];
                    uint2 b2 = wf[kk * 32];
                    mma_tf32(accB, a0, a1, a2, a3, b2.x, b2.y);
                }
            }
        }
        // K-split reduction
        if (khB == 1) {
            *(float4*)&sRed[(miB * 32 + lane) * 4] = make_float4(accB[0], accB[1], accB[2], accB[3]);
        }
        __syncthreads();
        if (khB == 0) {
            float4 p = *(const float4*)&sRed[(miB * 32 + lane) * 4];
            accB[0] += p.x; accB[1] += p.y; accB[2] += p.z; accB[3] += p.w;

            int b0 = miB * 16 + bR0, b1 = b0 + 8;
            int jc = j0 + jA2;
            float2 gh0 = *(const float2*)&gatesH[baseT + (size_t)b0 * HH + jc];
            float2 gh1 = *(const float2*)&gatesH[baseT + (size_t)b1 * HH + jc];
            float c00 = tanhf(gh0.x + accB[0]);
            float c01 = tanhf(gh0.y + accB[1]);
            float c10 = tanhf(gh1.x + accB[2]);
            float c11 = tanhf(gh1.y + accB[3]);
            float2 z0 = *(const float2*)&sZ[b0 * JPB + jA2];
            float2 z1 = *(const float2*)&sZ[b1 * JPB + jA2];
            float2 h0 = *(const float2*)&sHold[b0 * JPB + jA2];
            float2 h1 = *(const float2*)&sHold[b1 * JPB + jA2];
            float2 hn0 = make_float2(z0.x * h0.x + (1.f - z0.x) * c00,
                                     z0.y * h0.y + (1.f - z0.y) * c01);
            float2 hn1 = make_float2(z1.x * h1.x + (1.f - z1.x) * c10,
                                     z1.y * h1.y + (1.f - z1.y) * c11);
            *(float2*)&g_h[(size_t)b0 * HH + jc] = hn0;
            *(float2*)&g_h[(size_t)b1 * HH + jc] = hn1;
            *(float2*)&out[baseT + (size_t)b0 * HH + jc] = hn0;
            *(float2*)&out[baseT + (size_t)b1 * HH + jc] = hn1;
            if (hasFinal && t == TT - 1) {
                *(float2*)&finalOut[(size_t)b0 * HH + jc] = hn0;
                *(float2*)&finalOut[(size_t)b1 * HH + jc] = hn1;
            }
        }

        gridBarrier();   // new h published
    }
}

// ---------------------------------------------------------------------------
extern "C" void kernel_launch(void* const* d_in, const int* in_sizes, int n_in,
                              void* d_out, int out_size)
{
    const float* x      = (const float*)d_in[0];
    const float* state  = (const float*)d_in[1];
    const float* w_xr_w = (const float*)d_in[2];
    const float* w_xr_b = (const float*)d_in[3];
    const float* w_hr_w = (const float*)d_in[4];
    const float* w_xz_w = (const float*)d_in[5];
    const float* w_xz_b = (const float*)d_in[6];
    const float* w_hz_w = (const float*)d_in[7];
    const float* w_xh_w = (const float*)d_in[8];
    const float* w_xh_b = (const float*)d_in[9];
    const float* w_hh_w = (const float*)d_in[10];

    cudaFuncSetAttribute(gru_recurrent,
                         cudaFuncAttributeMaxDynamicSharedMemorySize, RSMEM_BYTES);

    dim3 gg(GN / 128, GM / 128, 3);
    mma_gate<<<gg, 256>>>(x, w_xr_w, w_xz_w, w_xh_w, w_xr_b, w_xz_b, w_xh_b);

    gru_recurrent<<<NBLK, RTHREADS, RSMEM_BYTES>>>(
        state, w_hr_w, w_hz_w, w_hh_w, (float*)d_out, out_size);
}

// round 5
// speedup vs baseline: 1.7882x; 1.2883x over previous
#include <cuda_runtime.h>
#include <cuda_bf16.h>
#include <cstdint>

// Problem constants
#define TT 512
#define BB 64
#define II 1024
#define HH 1024
#define GM (TT*BB)
#define GK II
#define GN HH

// Recurrent kernel config
#define NBLK 128
#define JPB  8
#define RTHREADS 256
#define HSTR 132          // 132 % 32 == 4 -> A-frag LDS fully conflict-free
#define RCHUNK 128
#define NCH (HH / RCHUNK) // 8

// Scratch
__device__ float g_gates[(size_t)3 * TT * BB * HH];
__device__ float g_h [(size_t)BB * HH];
__device__ float g_hr[(size_t)BB * HH];
__device__ unsigned g_bar_cnt;
__device__ unsigned g_bar_gen;

// ---------------------------------------------------------------------------
// Grid barrier: pure spin (all NBLK CTAs co-resident, 1/SM). No nanosleep.
// ---------------------------------------------------------------------------
__device__ __forceinline__ void gridBarrier() {
    __syncthreads();
    if (threadIdx.x == 0) {
        __threadfence();
        volatile unsigned* vgen = &g_bar_gen;
        unsigned gen = *vgen;
        if (atomicAdd(&g_bar_cnt, 1u) == NBLK - 1u) {
            g_bar_cnt = 0u;
            __threadfence();
            *vgen = gen + 1u;
        } else {
            while (*vgen == gen) { }
        }
        __threadfence();
    }
    __syncthreads();
}

__device__ __forceinline__ float sigmoidf_(float x) {
    return 1.0f / (1.0f + __expf(-x));
}

__device__ __forceinline__ uint32_t f2tf32(float x) {
    uint32_t r;
    asm("cvt.rna.tf32.f32 %0, %1;" : "=r"(r) : "f"(x));
    return r;
}

__device__ __forceinline__ void mma_tf32(float acc[4],
                                         uint32_t a0, uint32_t a1, uint32_t a2, uint32_t a3,
                                         uint32_t b0, uint32_t b1) {
    asm volatile(
        "mma.sync.aligned.m16n8k8.row.col.f32.tf32.tf32.f32 "
        "{%0,%1,%2,%3}, {%4,%5,%6,%7}, {%8,%9}, {%0,%1,%2,%3};"
        : "+f"(acc[0]), "+f"(acc[1]), "+f"(acc[2]), "+f"(acc[3])
        : "r"(a0), "r"(a1), "r"(a2), "r"(a3), "r"(b0), "r"(b1));
}

// ---------------------------------------------------------------------------
// TF32 input projection GEMM (unchanged, ~2ms)
// ---------------------------------------------------------------------------
#define BKT 32
#define SASTRIDE 136

__global__ __launch_bounds__(256) void mma_gate(
    const float* __restrict__ A,
    const float* __restrict__ W0, const float* __restrict__ W1, const float* __restrict__ W2,
    const float* __restrict__ b0, const float* __restrict__ b1, const float* __restrict__ b2)
{
    __shared__ uint32_t As[BKT * SASTRIDE];
    __shared__ uint32_t Ws[BKT * SASTRIDE];

    const int gate = blockIdx.z;
    const float* W    = (gate == 0) ? W0 : (gate == 1) ? W1 : W2;
    const float* bias = (gate == 0) ? b0 : (gate == 1) ? b1 : b2;
    float* C = g_gates + (size_t)gate * GM * GN;

    const int m0 = blockIdx.y * 128;
    const int n0 = blockIdx.x * 128;
    const int tid  = threadIdx.x;
    const int wid  = tid >> 5;
    const int lane = tid & 31;
    const int g  = lane >> 2;
    const int t4 = lane & 3;

    const int wm = (wid & 1) * 64;
    const int wn = (wid >> 1) * 32;

    float acc[4][4][4];
    #pragma unroll
    for (int mi = 0; mi < 4; ++mi)
        #pragma unroll
        for (int ni = 0; ni < 4; ++ni)
            #pragma unroll
            for (int r = 0; r < 4; ++r) acc[mi][ni][r] = 0.0f;

    for (int kt = 0; kt < GK; kt += BKT) {
        #pragma unroll
        for (int i = 0; i < 4; ++i) {
            int idx = tid + i * 256;
            int row = idx >> 3;
            int kc4 = (idx & 7) * 4;
            float4 a = *(const float4*)&A[(size_t)(m0 + row) * GK + kt + kc4];
            As[(kc4 + 0) * SASTRIDE + row] = f2tf32(a.x);
            As[(kc4 + 1) * SASTRIDE + row] = f2tf32(a.y);
            As[(kc4 + 2) * SASTRIDE + row] = f2tf32(a.z);
            As[(kc4 + 3) * SASTRIDE + row] = f2tf32(a.w);
            float4 w = *(const float4*)&W[(size_t)(n0 + row) * GK + kt + kc4];
            Ws[(kc4 + 0) * SASTRIDE + row] = f2tf32(w.x);
            Ws[(kc4 + 1) * SASTRIDE + row] = f2tf32(w.y);
            Ws[(kc4 + 2) * SASTRIDE + row] = f2tf32(w.z);
            Ws[(kc4 + 3) * SASTRIDE + row] = f2tf32(w.w);
        }
        __syncthreads();

        #pragma unroll
        for (int ks = 0; ks < BKT; ks += 8) {
            uint32_t af[4][4];
            #pragma unroll
            for (int mi = 0; mi < 4; ++mi) {
                int m = wm + mi * 16 + g;
                af[mi][0] = As[(ks + t4    ) * SASTRIDE + m    ];
                af[mi][1] = As[(ks + t4    ) * SASTRIDE + m + 8];
                af[mi][2] = As[(ks + t4 + 4) * SASTRIDE + m    ];
                af[mi][3] = As[(ks + t4 + 4) * SASTRIDE + m + 8];
            }
            uint32_t bf[4][2];
            #pragma unroll
            for (int ni = 0; ni < 4; ++ni) {
                int n = wn + ni * 8 + g;
                bf[ni][0] = Ws[(ks + t4    ) * SASTRIDE + n];
                bf[ni][1] = Ws[(ks + t4 + 4) * SASTRIDE + n];
            }
            #pragma unroll
            for (int mi = 0; mi < 4; ++mi)
                #pragma unroll
                for (int ni = 0; ni < 4; ++ni)
                    mma_tf32(acc[mi][ni], af[mi][0], af[mi][1], af[mi][2], af[mi][3],
                             bf[ni][0], bf[ni][1]);
        }
        __syncthreads();
    }

    #pragma unroll
    for (int mi = 0; mi < 4; ++mi) {
        int mrow = m0 + wm + mi * 16 + g;
        #pragma unroll
        for (int ni = 0; ni < 4; ++ni) {
            int col = n0 + wn + ni * 8 + 2 * t4;
            float bx = bias[col], by = bias[col + 1];
            float2 o0 = make_float2(acc[mi][ni][0] + bx, acc[mi][ni][1] + by);
            float2 o1 = make_float2(acc[mi][ni][2] + bx, acc[mi][ni][3] + by);
            *(float2*)&C[(size_t)mrow * GN + col] = o0;
            *(float2*)&C[(size_t)(mrow + 8) * GN + col] = o1;
        }
    }
}

// ---------------------------------------------------------------------------
// Tensor-core persistent recurrent kernel with cp.async double-buffered
// h staging, spin barrier, conflict-free frag stride.
// ---------------------------------------------------------------------------
#define OFF_WF   0
#define SZ_WF    (3 * 128 * 32 * 8)                 // 98304
#define OFF_SH0  (OFF_WF + SZ_WF)
#define SZ_SHB   (BB * HSTR * 4)                    // 33792 per buffer
#define OFF_SH1  (OFF_SH0 + SZ_SHB)
#define OFF_SZ   (OFF_SH1 + SZ_SHB)
#define SZ_SZ    (BB * JPB * 4)
#define OFF_SHO  (OFF_SZ + SZ_SZ)
#define OFF_SRED (OFF_SHO + SZ_SZ)
#define SZ_SRED  (4 * 32 * 4 * 4)
#define RSMEM_BYTES (OFF_SRED + SZ_SRED)            // 172032

__device__ __forceinline__ void stageAsync(uint32_t sbase, const float* __restrict__ src,
                                           int kc, int tid) {
    #pragma unroll
    for (int j = 0; j < 8; ++j) {
        int i  = tid + j * 256;        // 0..2047 (16B units)
        int b  = i >> 5;               // 32 x 16B per row
        int c4 = (i & 31) << 2;
        uint32_t dst = sbase + (unsigned)(b * HSTR + c4) * 4u;
        const float* gp = &src[(size_t)b * HH + kc + c4];
        asm volatile("cp.async.ca.shared.global [%0], [%1], 16;" :: "r"(dst), "l"(gp));
    }
    asm volatile("cp.async.commit_group;");
}

__global__ __launch_bounds__(RTHREADS, 1) void gru_recurrent(
    const float* __restrict__ state,
    const float* __restrict__ w_hr,
    const float* __restrict__ w_hz,
    const float* __restrict__ w_hh,
    float* __restrict__ out,
    int out_size)
{
    extern __shared__ char smem[];
    uint2*    uWf  = (uint2*)(smem + OFF_WF);
    uint32_t* sHg[2];
    sHg[0] = (uint32_t*)(smem + OFF_SH0);
    sHg[1] = (uint32_t*)(smem + OFF_SH1);
    float*    sZ    = (float*)(smem + OFF_SZ);
    float*    sHold = (float*)(smem + OFF_SHO);
    float*    sRed  = (float*)(smem + OFF_SRED);
    uint32_t sBuf[2];
    sBuf[0] = (uint32_t)__cvta_generic_to_shared(sHg[0]);
    sBuf[1] = (uint32_t)__cvta_generic_to_shared(sHg[1]);

    const int j0  = blockIdx.x * JPB;
    const int tid = threadIdx.x;
    const int wid = tid >> 5;
    const int lane = tid & 31;
    const int g  = lane >> 2;
    const int t4 = lane & 3;

    // ---- weights -> tf32 B-fragment order (once) ----
    {
        const float* Ws3[3] = {w_hr, w_hz, w_hh};
        for (int g3 = 0; g3 < 3; ++g3) {
            const float* W = Ws3[g3];
            for (int idx = tid; idx < 128 * 32; idx += RTHREADS) {
                int kk8 = idx >> 5;
                int ln  = idx & 31;
                int jj  = ln >> 2;
                int kk  = (kk8 << 3) + (ln & 3);
                uint2 v;
                v.x = f2tf32(W[(size_t)(j0 + jj) * HH + kk]);
                v.y = f2tf32(W[(size_t)(j0 + jj) * HH + kk + 4]);
                uWf[(g3 * 128 + kk8) * 32 + ln] = v;
            }
        }
    }

    // ---- init h ----
    for (int p = tid; p < BB * JPB; p += RTHREADS) {
        int b = p >> 3, jj = p & 7;
        g_h[(size_t)b * HH + j0 + jj] = state[(size_t)b * HH + j0 + jj];
    }
    gridBarrier();

    const float* gatesR = g_gates;
    const float* gatesZ = g_gates + (size_t)1 * TT * BB * HH;
    const float* gatesH = g_gates + (size_t)2 * TT * BB * HH;
    const bool hasFinal = (out_size >= (int)((size_t)TT * BB * HH + BB * HH));
    float* finalOut = out + (size_t)TT * BB * HH;

    const int miA = wid & 3;
    const int niA = wid >> 2;        // 0 = r gate, 1 = z gate
    const int m0A = miA * 16;
    const int miB = wid & 3;
    const int khB = wid >> 2;        // chunks 0-3 vs 4-7

    const int jA2 = 2 * t4;
    const int bA0 = m0A + g, bA1 = bA0 + 8;
    const int jc  = j0 + jA2;

    for (int t = 0; t < TT; ++t) {
        const size_t baseT = (size_t)t * BB * HH;

        // Prefetch epilogue-A operands (hide LDG latency under MMA)
        const float* gAB = (niA == 0) ? gatesR : gatesZ;
        float2 pg0 = *(const float2*)&gAB[baseT + (size_t)bA0 * HH + jc];
        float2 pg1 = *(const float2*)&gAB[baseT + (size_t)bA1 * HH + jc];
        float2 ho0 = *(const float2*)&g_h[(size_t)bA0 * HH + jc];
        float2 ho1 = *(const float2*)&g_h[(size_t)bA1 * HH + jc];

        // ================= Phase A: r and z =================
        float acc[4] = {0.f, 0.f, 0.f, 0.f};
        stageAsync(sBuf[0], g_h, 0, tid);
        #pragma unroll 1
        for (int c = 0; c < NCH; ++c) {
            if (c + 1 < NCH) {
                stageAsync(sBuf[(c + 1) & 1], g_h, (c + 1) * RCHUNK, tid);
                asm volatile("cp.async.wait_group 1;");
            } else {
                asm volatile("cp.async.wait_group 0;");
            }
            __syncthreads();
            const uint32_t* buf = sHg[c & 1];
            const uint32_t* hp0 = buf + bA0 * HSTR + t4;
            const uint32_t* hp1 = buf + bA1 * HSTR + t4;
            const uint2* wf = &uWf[(niA * 128 + (c * RCHUNK >> 3)) * 32 + lane];
            #pragma unroll
            for (int kk = 0; kk < RCHUNK / 8; ++kk) {
                uint32_t a0 = f2tf32(__uint_as_float(hp0[kk * 8]));
                uint32_t a1 = f2tf32(__uint_as_float(hp1[kk * 8]));
                uint32_t a2 = f2tf32(__uint_as_float(hp0[kk * 8 + 4]));
                uint32_t a3 = f2tf32(__uint_as_float(hp1[kk * 8 + 4]));
                uint2 b2 = wf[kk * 32];
                mma_tf32(acc, a0, a1, a2, a3, b2.x, b2.y);
            }
            __syncthreads();
        }

        // Epilogue A
        if (niA == 0) {
            float r00 = sigmoidf_(pg0.x + acc[0]);
            float r01 = sigmoidf_(pg0.y + acc[1]);
            float r10 = sigmoidf_(pg1.x + acc[2]);
            float r11 = sigmoidf_(pg1.y + acc[3]);
            *(float2*)&g_hr[(size_t)bA0 * HH + jc] = make_float2(ho0.x * r00, ho0.y * r01);
            *(float2*)&g_hr[(size_t)bA1 * HH + jc] = make_float2(ho1.x * r10, ho1.y * r11);
            *(float2*)&sHold[bA0 * JPB + jA2] = ho0;
            *(float2*)&sHold[bA1 * JPB + jA2] = ho1;
        } else {
            *(float2*)&sZ[bA0 * JPB + jA2] =
                make_float2(sigmoidf_(pg0.x + acc[0]), sigmoidf_(pg0.y + acc[1]));
            *(float2*)&sZ[bA1 * JPB + jA2] =
                make_float2(sigmoidf_(pg1.x + acc[2]), sigmoidf_(pg1.y + acc[3]));
        }

        gridBarrier();   // all hr published

        // Prefetch candidate gates
        float2 pgh0 = *(const float2*)&gatesH[baseT + (size_t)bA0 * HH + jc];
        float2 pgh1 = *(const float2*)&gatesH[baseT + (size_t)bA1 * HH + jc];

        // ================= Phase B: candidate =================
        float accB[4] = {0.f, 0.f, 0.f, 0.f};
        stageAsync(sBuf[0], g_hr, 0, tid);
        #pragma unroll 1
        for (int c = 0; c < NCH; ++c) {
            if (c + 1 < NCH) {
                stageAsync(sBuf[(c + 1) & 1], g_hr, (c + 1) * RCHUNK, tid);
                asm volatile("cp.async.wait_group 1;");
            } else {
                asm volatile("cp.async.wait_group 0;");
            }
            __syncthreads();
            if ((c >> 2) == khB) {
                const uint32_t* buf = sHg[c & 1];
                const uint32_t* hp0 = buf + (miB * 16 + g) * HSTR + t4;
                const uint32_t* hp1 = buf + (miB * 16 + g + 8) * HSTR + t4;
                const uint2* wf = &uWf[(2 * 128 + (c * RCHUNK >> 3)) * 32 + lane];
                #pragma unroll
                for (int kk = 0; kk < RCHUNK / 8; ++kk) {
                    uint32_t a0 = f2tf32(__uint_as_float(hp0[kk * 8]));
                    uint32_t a1 = f2tf32(__uint_as_float(hp1[kk * 8]));
                    uint32_t a2 = f2tf32(__uint_as_float(hp0[kk * 8 + 4]));
                    uint32_t a3 = f2tf32(__uint_as_float(hp1[kk * 8 + 4]));
                    uint2 b2 = wf[kk * 32];
                    mma_tf32(accB, a0, a1, a2, a3, b2.x, b2.y);
                }
            }
            __syncthreads();
        }

        if (khB == 1) {
            *(float4*)&sRed[(miB * 32 + lane) * 4] =
                make_float4(accB[0], accB[1], accB[2], accB[3]);
        }
        __syncthreads();
        if (khB == 0) {
            float4 p = *(const float4*)&sRed[(miB * 32 + lane) * 4];
            accB[0] += p.x; accB[1] += p.y; accB[2] += p.z; accB[3] += p.w;

            int b0 = miB * 16 + g, b1 = b0 + 8;
            float c00 = tanhf(pgh0.x + accB[0]);
            float c01 = tanhf(pgh0.y + accB[1]);
            float c10 = tanhf(pgh1.x + accB[2]);
            float c11 = tanhf(pgh1.y + accB[3]);
            float2 z0 = *(const float2*)&sZ[b0 * JPB + jA2];
            float2 z1 = *(const float2*)&sZ[b1 * JPB + jA2];
            float2 h0 = *(const float2*)&sHold[b0 * JPB + jA2];
            float2 h1 = *(const float2*)&sHold[b1 * JPB + jA2];
            float2 hn0 = make_float2(z0.x * h0.x + (1.f - z0.x) * c00,
                                     z0.y * h0.y + (1.f - z0.y) * c01);
            float2 hn1 = make_float2(z1.x * h1.x + (1.f - z1.x) * c10,
                                     z1.y * h1.y + (1.f - z1.y) * c11);
            *(float2*)&g_h[(size_t)b0 * HH + jc] = hn0;
            *(float2*)&g_h[(size_t)b1 * HH + jc] = hn1;
            *(float2*)&out[baseT + (size_t)b0 * HH + jc] = hn0;
            *(float2*)&out[baseT + (size_t)b1 * HH + jc] = hn1;
            if (hasFinal && t == TT - 1) {
                *(float2*)&finalOut[(size_t)b0 * HH + jc] = hn0;
                *(float2*)&finalOut[(size_t)b1 * HH + jc] = hn1;
            }
        }

        gridBarrier();   // new h published
    }
}

// ---------------------------------------------------------------------------
extern "C" void kernel_launch(void* const* d_in, const int* in_sizes, int n_in,
                              void* d_out, int out_size)
{
    const float* x      = (const float*)d_in[0];
    const float* state  = (const float*)d_in[1];
    const float* w_xr_w = (const float*)d_in[2];
    const float* w_xr_b = (const float*)d_in[3];
    const float* w_hr_w = (const float*)d_in[4];
    const float* w_xz_w = (const float*)d_in[5];
    const float* w_xz_b = (const float*)d_in[6];
    const float* w_hz_w = (const float*)d_in[7];
    const float* w_xh_w = (const float*)d_in[8];
    const float* w_xh_b = (const float*)d_in[9];
    const float* w_hh_w = (const float*)d_in[10];

    cudaFuncSetAttribute(gru_recurrent,
                         cudaFuncAttributeMaxDynamicSharedMemorySize, RSMEM_BYTES);

    dim3 gg(GN / 128, GM / 128, 3);
    mma_gate<<<gg, 256>>>(x, w_xr_w, w_xz_w, w_xh_w, w_xr_b, w_xz_b, w_xh_b);

    gru_recurrent<<<NBLK, RTHREADS, RSMEM_BYTES>>>(
        state, w_hr_w, w_hz_w, w_hh_w, (float*)d_out, out_size);
}